// round 15
// baseline (speedup 1.0000x reference)
#include <cuda_runtime.h>
#include <cuda_fp16.h>
#include <mma.h>
#include <cstdint>

using namespace nvcuda;

#define H        256
#define FOURH    1024
#define NG       2048
#define APG      64
#define GRIDA    444          // attention: 3 CTAs per SM
#define TILE_F   (APG*H)
#define TILE_B   (TILE_F*4)   // fp32 tile bytes
#define TILE_HB  (TILE_F*2)   // fp16 tile bytes

// ---------------- device scratch ----------------
__device__ __align__(128) __half g_Wc16[FOURH * H];      // fp16 folded weights
__device__ float   g_bc[FOURH];
__device__ float   g_q0[H];
__device__ float   g_c0[H];
__device__ float   g_c [NG * H];
__device__ __align__(128) __half g_h16[NG * H];          // fp16 h (= r)
__device__ float   g_gates[NG * FOURH];
__device__ __align__(128) __half2 g_xh2[(size_t)NG * 8192];  // fp16 copy of x

__device__ __forceinline__ float sigmoidf_(float v) {
    return 1.0f / (1.0f + __expf(-v));
}

__device__ __forceinline__ uint64_t policy_evict_first() {
    uint64_t p;
    asm("createpolicy.fractional.L2::evict_first.b64 %0, 1.0;" : "=l"(p));
    return p;
}
__device__ __forceinline__ uint64_t policy_evict_last() {
    uint64_t p;
    asm("createpolicy.fractional.L2::evict_last.b64 %0, 1.0;" : "=l"(p));
    return p;
}

// ---------------- prep ----------------
__global__ void prep_kernel(const float* __restrict__ W_ih,
                            const float* __restrict__ W_hh,
                            const float* __restrict__ b_ih,
                            const float* __restrict__ b_hh) {
    int idx = blockIdx.x * 256 + threadIdx.x;
    if (idx < FOURH * H)
        g_Wc16[idx] = __float2half(W_ih[idx] + W_hh[idx]);
    if (idx < FOURH) g_bc[idx] = b_ih[idx] + b_hh[idx];
    if (idx < H) {
        float gi = b_ih[idx]       + b_hh[idx];
        float gg = b_ih[512 + idx] + b_hh[512 + idx];
        float go = b_ih[768 + idx] + b_hh[768 + idx];
        float c  = sigmoidf_(gi) * tanhf(gg);
        g_c0[idx] = c;
        g_q0[idx] = sigmoidf_(go) * tanhf(c);
    }
}

// ---------------- GEMM: gates = h16 @ Wc16^T via wmma (fp32 accum) ----------------
#define GW_SMEM (2 * 128 * 256 * 2)   // A block + B block, fp16

__global__ void __launch_bounds__(256) gemm_wmma_kernel() {
    extern __shared__ __align__(16) __half smh[];
    __half* As = smh;                  // [128][256]
    __half* Bs = smh + 128 * 256;      // [128][256]  (rows = n, cols = k)

    int tid = threadIdx.x;
    int mb  = blockIdx.y * 128;
    int nb  = blockIdx.x * 128;

    {
        const uint4* srcA = (const uint4*)(g_h16  + (size_t)mb * H);
        const uint4* srcB = (const uint4*)(g_Wc16 + (size_t)nb * H);
        uint4* dA = (uint4*)As;
        uint4* dB = (uint4*)Bs;
        #pragma unroll
        for (int i = 0; i < 16; ++i) dA[tid + i * 256] = srcA[tid + i * 256];
        #pragma unroll
        for (int i = 0; i < 16; ++i) dB[tid + i * 256] = srcB[tid + i * 256];
    }
    __syncthreads();

    int w  = tid >> 5;
    int wm = (w >> 1) * 32;
    int wn = (w & 1) * 64;

    wmma::fragment<wmma::accumulator, 16, 16, 16, float> acc[2][4];
    #pragma unroll
    for (int i = 0; i < 2; ++i)
        #pragma unroll
        for (int j = 0; j < 4; ++j) wmma::fill_fragment(acc[i][j], 0.0f);

    #pragma unroll
    for (int k = 0; k < H; k += 16) {
        wmma::fragment<wmma::matrix_a, 16, 16, 16, __half, wmma::row_major> af[2];
        wmma::fragment<wmma::matrix_b, 16, 16, 16, __half, wmma::col_major> bf[4];
        #pragma unroll
        for (int i = 0; i < 2; ++i)
            wmma::load_matrix_sync(af[i], As + (wm + 16 * i) * H + k, H);
        #pragma unroll
        for (int j = 0; j < 4; ++j)
            wmma::load_matrix_sync(bf[j], Bs + (wn + 16 * j) * H + k, H);
        #pragma unroll
        for (int i = 0; i < 2; ++i)
            #pragma unroll
            for (int j = 0; j < 4; ++j)
                wmma::mma_sync(acc[i][j], af[i], bf[j], acc[i][j]);
    }

    #pragma unroll
    for (int i = 0; i < 2; ++i)
        #pragma unroll
        for (int j = 0; j < 4; ++j)
            wmma::store_matrix_sync(
                &g_gates[(size_t)(mb + wm + 16 * i) * FOURH + nb + wn + 16 * j],
                acc[i][j], FOURH, wmma::mem_row_major);
}

// ---------------- pass 0: fp32 attention (q = q0) + fp16 tile export ----------------
#define A32_FLOATS (TILE_F + H + APG + 512)
#define A32_SMEM   (A32_FLOATS*4 + 8)

__global__ void __launch_bounds__(512, 3) attn0_kernel(const float* __restrict__ x) {
    extern __shared__ __align__(16) unsigned char smraw[];
    float* xs  = (float*)smraw;              // [64][256] fp32
    float* qs  = xs + TILE_F;                // [256]
    float* sc  = qs + H;                     // [64]
    float* red = sc + APG;                   // [512]
    uint32_t smem_base;
    asm("{ .reg .u64 t; cvta.to.shared.u64 t, %1; cvt.u32.u64 %0, t; }"
        : "=r"(smem_base) : "l"(smraw));
    uint32_t mbar = smem_base + A32_FLOATS * 4;

    int tid  = threadIdx.x;
    int lane = tid & 31;
    int w    = tid >> 5;
    uint64_t pol_ef = policy_evict_first();

    if (tid == 0)
        asm volatile("mbarrier.init.shared.b64 [%0], 1;" :: "r"(mbar) : "memory");
    __syncthreads();

    int ph = 0;
    for (int b = blockIdx.x; b < NG; b += GRIDA) {
        if (tid == 0) {
            asm volatile("mbarrier.arrive.expect_tx.shared.b64 _, [%0], %1;"
                         :: "r"(mbar), "r"(TILE_B) : "memory");
            // streamed fp32 x: evict_first so it doesn't displace g_xh2
            asm volatile("cp.async.bulk.shared::cta.global.mbarrier::complete_tx::bytes.L2::cache_hint "
                         "[%0], [%1], %2, [%3], %4;"
                         :: "r"(smem_base), "l"(x + (size_t)b * TILE_F),
                            "r"(TILE_B), "r"(mbar), "l"(pol_ef) : "memory");
        }
        if (tid < H) qs[tid] = g_q0[tid];

        {
            uint32_t done;
            do {
                asm volatile(
                    "{ .reg .pred p; "
                    "mbarrier.try_wait.parity.acquire.cta.shared::cta.b64 p, [%1], %2, 0x989680; "
                    "selp.b32 %0, 1, 0, p; }"
                    : "=r"(done) : "r"(mbar), "r"(ph) : "memory");
            } while (!done);
            ph ^= 1;
        }
        __syncthreads();

        // export tile as fp16 with evict_last via 256-bit stores
        // (32 bytes = 16 floats per store; 512 thr x 2 iters = 32KB tile)
        {
            const float4* src4 = (const float4*)xs;
            #pragma unroll
            for (int it = 0; it < 2; ++it) {
                int g4 = tid + it * 512;          // group of 4 float4
                float4 v0 = src4[g4 * 4 + 0];
                float4 v1 = src4[g4 * 4 + 1];
                float4 v2 = src4[g4 * 4 + 2];
                float4 v3 = src4[g4 * 4 + 3];
                __half2 h0 = __floats2half2_rn(v0.x, v0.y);
                __half2 h1 = __floats2half2_rn(v0.z, v0.w);
                __half2 h2 = __floats2half2_rn(v1.x, v1.y);
                __half2 h3 = __floats2half2_rn(v1.z, v1.w);
                __half2 h4 = __floats2half2_rn(v2.x, v2.y);
                __half2 h5 = __floats2half2_rn(v2.z, v2.w);
                __half2 h6 = __floats2half2_rn(v3.x, v3.y);
                __half2 h7 = __floats2half2_rn(v3.z, v3.w);
                uint64_t d0 = ((uint64_t)*(uint32_t*)&h1 << 32) | *(uint32_t*)&h0;
                uint64_t d1 = ((uint64_t)*(uint32_t*)&h3 << 32) | *(uint32_t*)&h2;
                uint64_t d2 = ((uint64_t)*(uint32_t*)&h5 << 32) | *(uint32_t*)&h4;
                uint64_t d3 = ((uint64_t)*(uint32_t*)&h7 << 32) | *(uint32_t*)&h6;
                __half2* dst = g_xh2 + (size_t)b * 8192 + (size_t)g4 * 8;
                asm volatile("st.global.L2::evict_last.v4.b64 [%0], {%1, %2, %3, %4};"
                             :: "l"(dst), "l"(d0), "l"(d1), "l"(d2), "l"(d3)
                             : "memory");
            }
        }

        // scores: 16 warps x 4 atoms
        float qreg[8];
        #pragma unroll
        for (int k = 0; k < 8; ++k) qreg[k] = qs[lane + 32 * k];
        #pragma unroll
        for (int aa = 0; aa < 4; ++aa) {
            int a = w * 4 + aa;
            const float* xr = xs + a * H;
            float p = 0.0f;
            #pragma unroll
            for (int k = 0; k < 8; ++k)
                p = fmaf(xr[lane + 32 * k], qreg[k], p);
            #pragma unroll
            for (int off = 16; off; off >>= 1)
                p += __shfl_xor_sync(0xffffffffu, p, off);
            if (lane == 0) sc[a] = p;
        }
        __syncthreads();

        // softmax over 64 (warp 0)
        if (w == 0) {
            float v0 = sc[lane], v1 = sc[lane + 32];
            float mx = fmaxf(v0, v1);
            #pragma unroll
            for (int off = 16; off; off >>= 1)
                mx = fmaxf(mx, __shfl_xor_sync(0xffffffffu, mx, off));
            float e0 = __expf(v0 - mx), e1 = __expf(v1 - mx);
            float s = e0 + e1;
            #pragma unroll
            for (int off = 16; off; off >>= 1)
                s += __shfl_xor_sync(0xffffffffu, s, off);
            float inv = 1.0f / s;
            sc[lane]      = e0 * inv;
            sc[lane + 32] = e1 * inv;
        }
        __syncthreads();

        // weighted sum
        {
            int j    = tid & (H - 1);
            int half = tid >> 8;
            const float* Xh = xs + half * 32 * H;
            float r = 0.0f;
            #pragma unroll
            for (int a0 = 0; a0 < 32; ++a0)
                r = fmaf(sc[half * 32 + a0], Xh[a0 * H + j], r);
            red[tid] = r;
        }
        __syncthreads();
        if (tid < H)
            g_h16[(size_t)b * H + tid] = __float2half(red[tid] + red[tid + H]);
        __syncthreads();
    }
}

// ---------------- passes 1-2: fp16 attention (x from L2) ----------------
#define A16_BYTES  (TILE_HB + (H + APG + 1024)*4 + 8)

__global__ void __launch_bounds__(512, 3) attnh_kernel(float* __restrict__ out,
                                                       int mode) {
    extern __shared__ __align__(16) unsigned char smraw[];
    __half2* xsh = (__half2*)smraw;                    // [64][128]
    float* qs  = (float*)(smraw + TILE_HB);            // [256]
    float* sc  = qs + H;                               // [64]
    float* red = sc + APG;                             // [512] float2
    uint32_t smem_base;
    asm("{ .reg .u64 t; cvta.to.shared.u64 t, %1; cvt.u32.u64 %0, t; }"
        : "=r"(smem_base) : "l"(smraw));
    uint32_t mbar = smem_base + (uint32_t)(TILE_HB + (H + APG + 1024) * 4);

    int tid  = threadIdx.x;
    int lane = tid & 31;
    int w    = tid >> 5;
    uint64_t pol_el = policy_evict_last();

    if (tid == 0)
        asm volatile("mbarrier.init.shared.b64 [%0], 1;" :: "r"(mbar) : "memory");
    __syncthreads();

    int ph = 0;
    for (int b = blockIdx.x; b < NG; b += GRIDA) {
        if (tid == 0) {
            asm volatile("mbarrier.arrive.expect_tx.shared.b64 _, [%0], %1;"
                         :: "r"(mbar), "r"(TILE_HB) : "memory");
            asm volatile("cp.async.bulk.shared::cta.global.mbarrier::complete_tx::bytes.L2::cache_hint "
                         "[%0], [%1], %2, [%3], %4;"
                         :: "r"(smem_base), "l"(g_xh2 + (size_t)b * 8192),
                            "r"(TILE_HB), "r"(mbar), "l"(pol_el) : "memory");
        }

        // fused LSTM pointwise -> q (overlaps TMA)
        if (tid < H) {
            int j = tid;
            const float* gr = g_gates + (size_t)b * FOURH;
            float gi = gr[j]       + g_bc[j];
            float gf = gr[256 + j] + g_bc[256 + j];
            float gg = gr[512 + j] + g_bc[512 + j];
            float go = gr[768 + j] + g_bc[768 + j];
            float cp = (mode == 1) ? g_c0[j] : g_c[(size_t)b * H + j];
            float c  = sigmoidf_(gf) * cp + sigmoidf_(gi) * tanhf(gg);
            float q  = sigmoidf_(go) * tanhf(c);
            if (mode == 1) g_c[(size_t)b * H + j] = c;
            if (mode == 2) out[(size_t)b * (2 * H) + j] = q;
            qs[j] = q;
        }

        {
            uint32_t done;
            do {
                asm volatile(
                    "{ .reg .pred p; "
                    "mbarrier.try_wait.parity.acquire.cta.shared::cta.b64 p, [%1], %2, 0x989680; "
                    "selp.b32 %0, 1, 0, p; }"
                    : "=r"(done) : "r"(mbar), "r"(ph) : "memory");
            } while (!done);
            ph ^= 1;
        }
        __syncthreads();

        // scores: 16 warps x 4 atoms; fp16 x, fp32 accumulate
        float2 q0 = *(const float2*)&qs[2 * lane];
        float2 q1 = *(const float2*)&qs[64 + 2 * lane];
        float2 q2 = *(const float2*)&qs[128 + 2 * lane];
        float2 q3 = *(const float2*)&qs[192 + 2 * lane];
        #pragma unroll
        for (int aa = 0; aa < 4; ++aa) {
            int a = w * 4 + aa;
            const __half2* row = xsh + a * 128;
            float2 x0 = __half22float2(row[lane]);
            float2 x1 = __half22float2(row[32 + lane]);
            float2 x2 = __half22float2(row[64 + lane]);
            float2 x3 = __half22float2(row[96 + lane]);
            float p = x0.x*q0.x + x0.y*q0.y + x1.x*q1.x + x1.y*q1.y
                    + x2.x*q2.x + x2.y*q2.y + x3.x*q3.x + x3.y*q3.y;
            #pragma unroll
            for (int off = 16; off; off >>= 1)
                p += __shfl_xor_sync(0xffffffffu, p, off);
            if (lane == 0) sc[a] = p;
        }
        __syncthreads();

        // softmax over 64 (warp 0)
        if (w == 0) {
            float v0 = sc[lane], v1 = sc[lane + 32];
            float mx = fmaxf(v0, v1);
            #pragma unroll
            for (int off = 16; off; off >>= 1)
                mx = fmaxf(mx, __shfl_xor_sync(0xffffffffu, mx, off));
            float e0 = __expf(v0 - mx), e1 = __expf(v1 - mx);
            float s = e0 + e1;
            #pragma unroll
            for (int off = 16; off; off >>= 1)
                s += __shfl_xor_sync(0xffffffffu, s, off);
            float inv = 1.0f / s;
            sc[lane]      = e0 * inv;
            sc[lane + 32] = e1 * inv;
        }
        __syncthreads();

        // weighted sum: thread -> feature pair, quarter of atoms
        {
            int fp = tid & 127;
            int qt = tid >> 7;
            float2 r2 = make_float2(0.0f, 0.0f);
            const __half2* Xq = xsh + qt * 16 * 128 + fp;
            #pragma unroll
            for (int a = 0; a < 16; ++a) {
                float sw = sc[qt * 16 + a];
                float2 xv = __half22float2(Xq[a * 128]);
                r2.x = fmaf(sw, xv.x, r2.x);
                r2.y = fmaf(sw, xv.y, r2.y);
            }
            *(float2*)&red[tid * 2] = r2;
        }
        __syncthreads();
        if (tid < 128) {
            float2 r0 = *(const float2*)&red[tid * 2];
            float2 r1 = *(const float2*)&red[(tid + 128) * 2];
            float2 r2 = *(const float2*)&red[(tid + 256) * 2];
            float2 r3 = *(const float2*)&red[(tid + 384) * 2];
            float2 rr = make_float2(r0.x + r1.x + r2.x + r3.x,
                                    r0.y + r1.y + r2.y + r3.y);
            ((__half2*)g_h16)[(size_t)b * 128 + tid] = __floats2half2_rn(rr.x, rr.y);
            if (mode == 2)
                *(float2*)&out[(size_t)b * (2 * H) + H + 2 * tid] = rr;
        }
        __syncthreads();
    }
}

// ---------------- launch ----------------
extern "C" void kernel_launch(void* const* d_in, const int* in_sizes, int n_in,
                              void* d_out, int out_size) {
    const float* x    = (const float*)d_in[0];
    const float* W_ih = (const float*)d_in[3];
    const float* W_hh = (const float*)d_in[4];
    const float* b_ih = (const float*)d_in[5];
    const float* b_hh = (const float*)d_in[6];
    float* out = (float*)d_out;

    cudaFuncSetAttribute(attn0_kernel,
                         cudaFuncAttributeMaxDynamicSharedMemorySize, (int)A32_SMEM);
    cudaFuncSetAttribute(attnh_kernel,
                         cudaFuncAttributeMaxDynamicSharedMemorySize, (int)A16_BYTES);
    cudaFuncSetAttribute(gemm_wmma_kernel,
                         cudaFuncAttributeMaxDynamicSharedMemorySize, (int)GW_SMEM);

    prep_kernel<<<1024, 256>>>(W_ih, W_hh, b_ih, b_hh);

    dim3 ggrid(FOURH / 128, NG / 128);

    attn0_kernel<<<GRIDA, 512, A32_SMEM>>>(x);                 // step 0 + fp16 export
    gemm_wmma_kernel<<<ggrid, 256, GW_SMEM>>>();
    attnh_kernel<<<GRIDA, 512, A16_BYTES>>>(nullptr, 1);       // step 1 (L2 x)
    gemm_wmma_kernel<<<ggrid, 256, GW_SMEM>>>();
    attnh_kernel<<<GRIDA, 512, A16_BYTES>>>(out, 2);           // step 2 (L2 x)
}